// round 4
// baseline (speedup 1.0000x reference)
#include <cuda_runtime.h>
#include <cstdint>

#define NN 100000
#define NE 1200000
#define NG 256
#define HID 64
#define INC 5

// -------- scratch (device globals; no allocation allowed) --------
__device__ __align__(256) float g_bufA[NN * HID];   // lin1 -> h1
__device__ __align__(256) float g_bufB[NN * HID];   // agg (both layers)
__device__ __align__(256) float g_bufC[NN * HID];   // lin2
__device__ __align__(256) float g_deg[NN];
__device__ __align__(256) float g_dinv[NN];
__device__ __align__(256) float g_pooled[NG * HID];
__device__ __align__(256) float g_cnt[NG];

__device__ __forceinline__ void red4(float* p, float a, float b, float c, float d) {
    asm volatile("red.global.add.v4.f32 [%0], {%1,%2,%3,%4};"
                 :: "l"(p), "f"(a), "f"(b), "f"(c), "f"(d) : "memory");
}

// -------- zero scratch (pre-pass: bufB + deg + pooled + cnt) --------
__global__ void k_zero_pre() {
    int i = blockIdx.x * blockDim.x + threadIdx.x;   // over NN*16 float4s
    if (i < NN * 16) ((float4*)g_bufB)[i] = make_float4(0.f, 0.f, 0.f, 0.f);
    if (i < NN) g_deg[i] = 0.f;
    if (i < NG * HID) g_pooled[i] = 0.f;
    if (i < NG) g_cnt[i] = 0.f;
}

__global__ void k_zero_B() {
    int i = blockIdx.x * blockDim.x + threadIdx.x;
    if (i < NN * 16) ((float4*)g_bufB)[i] = make_float4(0.f, 0.f, 0.f, 0.f);
}

// -------- degree (incoming edges; self-loop added in dinv) --------
__global__ void k_deg(const int* __restrict__ dst) {
    int e = blockIdx.x * blockDim.x + threadIdx.x;
    if (e >= NE) return;
    atomicAdd(&g_deg[dst[e]], 1.0f);
}

__global__ void k_dinv() {
    int i = blockIdx.x * blockDim.x + threadIdx.x;
    if (i >= NN) return;
    g_dinv[i] = rsqrtf(g_deg[i] + 1.0f);   // +1 = self-loop; always > 0
}

// -------- lin1: bufA = x @ W1   (K=5) --------
__global__ void k_lin1(const float* __restrict__ x, const float* __restrict__ W1) {
    int idx = blockIdx.x * blockDim.x + threadIdx.x;   // n*64 + c
    if (idx >= NN * HID) return;
    int n = idx >> 6, c = idx & 63;
    const float* xr = x + n * INC;
    float acc = 0.f;
#pragma unroll
    for (int k = 0; k < INC; k++) acc += __ldg(xr + k) * __ldg(W1 + k * HID + c);
    g_bufA[idx] = acc;
}

// -------- lin2: bufC = bufA @ W2  (64x64, W2 in smem, 8 outputs/thread) ----
__global__ void k_lin2(const float* __restrict__ W2) {
    __shared__ float Ws[HID * HID];
    for (int i = threadIdx.x; i < HID * HID; i += blockDim.x) Ws[i] = W2[i];
    __syncthreads();
    int t = blockIdx.x * blockDim.x + threadIdx.x;     // (n, group-of-8)
    int n = t >> 3;
    if (n >= NN) return;
    int g8 = (t & 7) * 8;
    const float* hr = g_bufA + (size_t)n * HID;
    float a0 = 0, a1 = 0, a2 = 0, a3 = 0, a4 = 0, a5 = 0, a6 = 0, a7 = 0;
#pragma unroll 8
    for (int k = 0; k < HID; k++) {
        float hv = __ldg(hr + k);
        float4 w0 = *(const float4*)(Ws + k * HID + g8);
        float4 w1 = *(const float4*)(Ws + k * HID + g8 + 4);
        a0 += hv * w0.x; a1 += hv * w0.y; a2 += hv * w0.z; a3 += hv * w0.w;
        a4 += hv * w1.x; a5 += hv * w1.y; a6 += hv * w1.z; a7 += hv * w1.w;
    }
    float* o = g_bufC + (size_t)n * HID + g8;
    *(float4*)o       = make_float4(a0, a1, a2, a3);
    *(float4*)(o + 4) = make_float4(a4, a5, a6, a7);
}

// -------- edge aggregation: agg[dst] += h[src] * dinv[src]*dinv[dst] ------
// 16 lanes per edge, one v4 load + one v4 red each.
__global__ void k_edge(const int* __restrict__ src,
                       const int* __restrict__ dst, int which) {
    int t = blockIdx.x * blockDim.x + threadIdx.x;
    int e = t >> 4;
    if (e >= NE) return;
    int l = t & 15;
    const float* h = which ? g_bufC : g_bufA;
    int s = __ldg(src + e);
    int d = __ldg(dst + e);
    float w = g_dinv[s] * g_dinv[d];
    float4 v = *(const float4*)(h + (size_t)s * HID + l * 4);
    float* ap = g_bufB + (size_t)d * HID + l * 4;
    red4(ap, v.x * w, v.y * w, v.z * w, v.w * w);
}

// -------- layer-1 epilogue: h1 = relu(agg + lin*dinv^2 + b1) -> bufA ------
__global__ void k_relu1(const float* __restrict__ b1) {
    int i = blockIdx.x * blockDim.x + threadIdx.x;   // over NN*16 float4s
    if (i >= NN * 16) return;
    int n = i >> 4, l = i & 15;
    float di = g_dinv[n];
    float w = di * di;
    float4 a = ((const float4*)g_bufA)[i];
    float4 b = ((const float4*)g_bufB)[i];
    float4 bb = ((const float4*)b1)[l];
    float4 r;
    r.x = fmaxf(b.x + a.x * w + bb.x, 0.f);
    r.y = fmaxf(b.y + a.y * w + bb.y, 0.f);
    r.z = fmaxf(b.z + a.z * w + bb.z, 0.f);
    r.w = fmaxf(b.w + a.w * w + bb.w, 0.f);
    ((float4*)g_bufA)[i] = r;
}

// -------- layer-2 epilogue fused with mean-pool scatter -------------------
__global__ void k_pool(const float* __restrict__ b2,
                       const int* __restrict__ batch) {
    int t = blockIdx.x * blockDim.x + threadIdx.x;   // over NN*16
    int n = t >> 4;
    if (n >= NN) return;
    int l = t & 15;
    int g = __ldg(batch + n);
    float di = g_dinv[n];
    float w = di * di;
    float4 c = ((const float4*)g_bufC)[n * 16 + l];
    float4 b = ((const float4*)g_bufB)[n * 16 + l];
    float4 bb = ((const float4*)b2)[l];
    float hx = fmaxf(b.x + c.x * w + bb.x, 0.f);
    float hy = fmaxf(b.y + c.y * w + bb.y, 0.f);
    float hz = fmaxf(b.z + c.z * w + bb.z, 0.f);
    float hw = fmaxf(b.w + c.w * w + bb.w, 0.f);
    red4(&g_pooled[g * HID + l * 4], hx, hy, hz, hw);
    if (l == 0) atomicAdd(&g_cnt[g], 1.0f);
}

// -------- final: out[g][o] = (pooled[g]@Wfc)[o]/cnt[g] + bfc[o] -----------
__global__ void k_final(const float* __restrict__ Wfc,
                        const float* __restrict__ bfc,
                        float* __restrict__ out) {
    int t = threadIdx.x;                // 512 threads: (g, o)
    int g = t >> 1, o = t & 1;
    float acc = 0.f;
#pragma unroll
    for (int c = 0; c < HID; c++)
        acc += g_pooled[g * HID + c] * __ldg(Wfc + c * 2 + o);
    float cnt = fmaxf(g_cnt[g], 1.0f);
    out[g * 2 + o] = acc / cnt + __ldg(bfc + o);
}

extern "C" void kernel_launch(void* const* d_in, const int* in_sizes, int n_in,
                              void* d_out, int out_size) {
    const float* x     = (const float*)d_in[0];
    const int*   ei    = (const int*)d_in[1];     // int32: JAX x64-disabled downcast
    const int*   batch = (const int*)d_in[2];
    const float* W1    = (const float*)d_in[3];
    const float* b1    = (const float*)d_in[4];
    const float* W2    = (const float*)d_in[5];
    const float* b2    = (const float*)d_in[6];
    const float* Wfc   = (const float*)d_in[7];
    const float* bfc   = (const float*)d_in[8];
    float*       out   = (float*)d_out;

    const int* src = ei;
    const int* dst = ei + NE;

    const int T = 256;
    k_zero_pre<<<(NN * 16 + T - 1) / T, T>>>();
    k_deg<<<(NE + T - 1) / T, T>>>(dst);
    k_dinv<<<(NN + T - 1) / T, T>>>();
    k_lin1<<<(NN * HID + T - 1) / T, T>>>(x, W1);
    k_edge<<<(NE * 16 + T - 1) / T, T>>>(src, dst, 0);
    k_relu1<<<(NN * 16 + T - 1) / T, T>>>(b1);
    k_zero_B<<<(NN * 16 + T - 1) / T, T>>>();
    k_lin2<<<(NN * 8 + T - 1) / T, T>>>(W2);
    k_edge<<<(NE * 16 + T - 1) / T, T>>>(src, dst, 1);
    k_pool<<<(NN * 16 + T - 1) / T, T>>>(b2, batch);
    k_final<<<1, 512>>>(Wfc, bfc, out);
}

// round 6
// speedup vs baseline: 1.1912x; 1.1912x over previous
#include <cuda_runtime.h>
#include <cstdint>

#define NN 100000
#define NE 1200000
#define NG 256
#define HID 64
#define INC 5

// -------- scratch (device globals; no allocation allowed) --------
__device__ __align__(256) float g_bufA[NN * HID];   // lin1 -> h1
__device__ __align__(256) float g_bufB[NN * HID];   // agg (both layers)
__device__ __align__(256) float g_bufC[NN * HID];   // lin2
__device__ __align__(256) float g_deg[NN];
__device__ __align__(256) float g_dinv[NN];
__device__ __align__(256) float g_w[NE];            // per-edge norm, computed in pass 0
__device__ __align__(256) float g_pooled[NG * HID];
__device__ __align__(256) float g_cnt[NG];

__device__ __forceinline__ void red4(float* p, float a, float b, float c, float d) {
    asm volatile("red.global.add.v4.f32 [%0], {%1,%2,%3,%4};"
                 :: "l"(p), "f"(a), "f"(b), "f"(c), "f"(d) : "memory");
}

// -------- zero scratch --------
__global__ void k_zero_pre() {
    int i = blockIdx.x * blockDim.x + threadIdx.x;   // over NN*16 float4s
    if (i < NN * 16) ((float4*)g_bufB)[i] = make_float4(0.f, 0.f, 0.f, 0.f);
    if (i < NN) g_deg[i] = 0.f;
    if (i < NG * HID) g_pooled[i] = 0.f;
    if (i < NG) g_cnt[i] = 0.f;
}

// -------- degree (incoming edges; self-loop added in dinv) --------
__global__ void k_deg(const int* __restrict__ dst) {
    int e = blockIdx.x * blockDim.x + threadIdx.x;
    if (e >= NE) return;
    atomicAdd(&g_deg[dst[e]], 1.0f);
}

__global__ void k_dinv() {
    int i = blockIdx.x * blockDim.x + threadIdx.x;
    if (i >= NN) return;
    g_dinv[i] = rsqrtf(g_deg[i] + 1.0f);   // +1 = self-loop; always > 0
}

// -------- lin1: bufA = x @ W1 (K=5); 4 channels per thread --------
__global__ void k_lin1(const float* __restrict__ x, const float* __restrict__ W1) {
    int idx = blockIdx.x * blockDim.x + threadIdx.x;   // over NN*16
    if (idx >= NN * 16) return;
    int n = idx >> 4, c4 = (idx & 15) * 4;
    float xr[INC];
#pragma unroll
    for (int k = 0; k < INC; k++) xr[k] = __ldg(x + n * INC + k);
    float4 acc = make_float4(0.f, 0.f, 0.f, 0.f);
#pragma unroll
    for (int k = 0; k < INC; k++) {
        float4 w = __ldg((const float4*)(W1 + k * HID + c4));
        acc.x += xr[k] * w.x; acc.y += xr[k] * w.y;
        acc.z += xr[k] * w.z; acc.w += xr[k] * w.w;
    }
    *(float4*)(g_bufA + (size_t)n * HID + c4) = acc;
}

// -------- lin2: bufC = bufA @ W2. 64 nodes/block, 128 thr:
//          thread = (node-group 0..15) x (8-channel group 0..7), 4 nodes each.
__global__ void __launch_bounds__(128) k_lin2(const float* __restrict__ W2) {
    __shared__ float Ws[HID * HID];
    for (int i = threadIdx.x; i < HID * HID; i += 128) Ws[i] = W2[i];
    __syncthreads();
    int nb = blockIdx.x * 64;
    int ng = threadIdx.x >> 3;            // 0..15
    int c8 = (threadIdx.x & 7) * 8;       // channel base
    int n0 = nb + ng;                     // nodes n0 + {0,16,32,48}
    const float* h0 = g_bufA + (size_t)min(n0,      NN - 1) * HID;
    const float* h1 = g_bufA + (size_t)min(n0 + 16, NN - 1) * HID;
    const float* h2 = g_bufA + (size_t)min(n0 + 32, NN - 1) * HID;
    const float* h3 = g_bufA + (size_t)min(n0 + 48, NN - 1) * HID;
    float a[4][8];
#pragma unroll
    for (int j = 0; j < 4; j++)
#pragma unroll
        for (int c = 0; c < 8; c++) a[j][c] = 0.f;
#pragma unroll 4
    for (int k = 0; k < HID; k++) {
        float4 w0 = *(const float4*)(Ws + k * HID + c8);
        float4 w1 = *(const float4*)(Ws + k * HID + c8 + 4);
        float hv[4] = {__ldg(h0 + k), __ldg(h1 + k), __ldg(h2 + k), __ldg(h3 + k)};
#pragma unroll
        for (int j = 0; j < 4; j++) {
            a[j][0] += hv[j] * w0.x; a[j][1] += hv[j] * w0.y;
            a[j][2] += hv[j] * w0.z; a[j][3] += hv[j] * w0.w;
            a[j][4] += hv[j] * w1.x; a[j][5] += hv[j] * w1.y;
            a[j][6] += hv[j] * w1.z; a[j][7] += hv[j] * w1.w;
        }
    }
#pragma unroll
    for (int j = 0; j < 4; j++) {
        int n = n0 + 16 * j;
        if (n < NN) {
            float* o = g_bufC + (size_t)n * HID + c8;
            *(float4*)o       = make_float4(a[j][0], a[j][1], a[j][2], a[j][3]);
            *(float4*)(o + 4) = make_float4(a[j][4], a[j][5], a[j][6], a[j][7]);
        }
    }
}

// -------- edge aggregation: agg[dst] += h[src] * w[e] ------
// 16 lanes per edge; lane 0 loads indices/weight, shfl broadcast.
// Grid is exact: NE*16 threads, no partial warps.
__global__ void k_edge(const int* __restrict__ src,
                       const int* __restrict__ dst, int which) {
    int t = blockIdx.x * blockDim.x + threadIdx.x;
    int e = t >> 4;
    int l = t & 15;
    int base = (threadIdx.x & 31) & ~15;   // lane base of this 16-group
    int s = 0, d = 0; float w = 0.f;
    if (l == 0) {
        s = __ldg(src + e);
        d = __ldg(dst + e);
        if (which == 0) { w = g_dinv[s] * g_dinv[d]; g_w[e] = w; }
        else            { w = __ldg(g_w + e); }
    }
    s = __shfl_sync(0xffffffffu, s, base);
    d = __shfl_sync(0xffffffffu, d, base);
    w = __shfl_sync(0xffffffffu, w, base);
    const float* h = which ? g_bufC : g_bufA;
    float4 v = *(const float4*)(h + (size_t)s * HID + l * 4);
    red4(g_bufB + (size_t)d * HID + l * 4, v.x * w, v.y * w, v.z * w, v.w * w);
}

// -------- layer-1 epilogue: h1 = relu(agg + lin*dinv^2 + b1) -> bufA,
//          and re-zero bufB for layer 2 ------
__global__ void k_relu1z(const float* __restrict__ b1) {
    int i = blockIdx.x * blockDim.x + threadIdx.x;   // over NN*16 float4s
    if (i >= NN * 16) return;
    int n = i >> 4, l = i & 15;
    float di = g_dinv[n];
    float w = di * di;
    float4 a = ((const float4*)g_bufA)[i];
    float4 b = ((const float4*)g_bufB)[i];
    float4 bb = __ldg((const float4*)b1 + l);
    float4 r;
    r.x = fmaxf(b.x + a.x * w + bb.x, 0.f);
    r.y = fmaxf(b.y + a.y * w + bb.y, 0.f);
    r.z = fmaxf(b.z + a.z * w + bb.z, 0.f);
    r.w = fmaxf(b.w + a.w * w + bb.w, 0.f);
    ((float4*)g_bufA)[i] = r;
    ((float4*)g_bufB)[i] = make_float4(0.f, 0.f, 0.f, 0.f);
}

// -------- layer-2 epilogue fused with mean-pool scatter -------------------
__global__ void k_pool(const float* __restrict__ b2,
                       const int* __restrict__ batch) {
    int t = blockIdx.x * blockDim.x + threadIdx.x;   // over NN*16
    int n = t >> 4;
    if (n >= NN) return;
    int l = t & 15;
    int g = __ldg(batch + n);
    float di = g_dinv[n];
    float w = di * di;
    float4 c = ((const float4*)g_bufC)[n * 16 + l];
    float4 b = ((const float4*)g_bufB)[n * 16 + l];
    float4 bb = __ldg((const float4*)b2 + l);
    float hx = fmaxf(b.x + c.x * w + bb.x, 0.f);
    float hy = fmaxf(b.y + c.y * w + bb.y, 0.f);
    float hz = fmaxf(b.z + c.z * w + bb.z, 0.f);
    float hw = fmaxf(b.w + c.w * w + bb.w, 0.f);
    red4(&g_pooled[g * HID + l * 4], hx, hy, hz, hw);
    if (l == 0) atomicAdd(&g_cnt[g], 1.0f);
}

// -------- final: out[g][o] = (pooled[g]@Wfc)[o]/cnt[g] + bfc[o] -----------
__global__ void k_final(const float* __restrict__ Wfc,
                        const float* __restrict__ bfc,
                        float* __restrict__ out) {
    int t = threadIdx.x;                // 512 threads: (g, o)
    int g = t >> 1, o = t & 1;
    float acc = 0.f;
#pragma unroll
    for (int c = 0; c < HID; c++)
        acc += g_pooled[g * HID + c] * __ldg(Wfc + c * 2 + o);
    float cnt = fmaxf(g_cnt[g], 1.0f);
    out[g * 2 + o] = acc / cnt + __ldg(bfc + o);
}

extern "C" void kernel_launch(void* const* d_in, const int* in_sizes, int n_in,
                              void* d_out, int out_size) {
    const float* x     = (const float*)d_in[0];
    const int*   ei    = (const int*)d_in[1];     // int32 (JAX x64 disabled)
    const int*   batch = (const int*)d_in[2];
    const float* W1    = (const float*)d_in[3];
    const float* b1    = (const float*)d_in[4];
    const float* W2    = (const float*)d_in[5];
    const float* b2    = (const float*)d_in[6];
    const float* Wfc   = (const float*)d_in[7];
    const float* bfc   = (const float*)d_in[8];
    float*       out   = (float*)d_out;

    const int* src = ei;
    const int* dst = ei + NE;

    const int T = 256;
    k_zero_pre<<<(NN * 16 + T - 1) / T, T>>>();
    k_deg<<<(NE + T - 1) / T, T>>>(dst);
    k_dinv<<<(NN + T - 1) / T, T>>>();
    k_lin1<<<(NN * 16 + T - 1) / T, T>>>(x, W1);
    k_edge<<<(NE * 16) / T, T>>>(src, dst, 0);
    k_relu1z<<<(NN * 16 + T - 1) / T, T>>>(b1);
    k_lin2<<<(NN + 63) / 64, 128>>>(W2);
    k_edge<<<(NE * 16) / T, T>>>(src, dst, 1);
    k_pool<<<(NN * 16 + T - 1) / T, T>>>(b2, batch);
    k_final<<<1, 512>>>(Wfc, bfc, out);
}

// round 9
// speedup vs baseline: 1.7553x; 1.4736x over previous
#include <cuda_runtime.h>
#include <cstdint>

#define NN 100000
#define NE 1200000
#define NG 256
#define HID 64
#define INC 5
#define NBLK ((NN + 255) / 256)   // 391 scan blocks

// -------- scratch (device globals; no allocation allowed) --------
__device__ __align__(256) float g_bufA[NN * HID];   // lin1 output
__device__ __align__(256) float g_bufB[NN * HID];   // h1 (relu'd)
__device__ __align__(256) float g_bufC[NN * HID];   // lin2 output
__device__ __align__(256) int   g_degi[NN];
__device__ __align__(256) int   g_rowptr[NN];
__device__ __align__(256) int   g_cursor[NN];
__device__ __align__(256) int   g_bsum[512];
__device__ __align__(256) float g_dinv[NN];
__device__ __align__(256) uint2 g_csr[NE];          // (src, w) per edge, dst-grouped
__device__ __align__(256) float g_pooled[NG * HID];
__device__ __align__(256) float g_cnt[NG];

__device__ __forceinline__ void red4(float* p, float a, float b, float c, float d) {
    asm volatile("red.global.add.v4.f32 [%0], {%1,%2,%3,%4};"
                 :: "l"(p), "f"(a), "f"(b), "f"(c), "f"(d) : "memory");
}

// -------- init: zero degi + pooled + cnt --------
__global__ void k_init() {
    int i = blockIdx.x * blockDim.x + threadIdx.x;
    if (i < NN) g_degi[i] = 0;
    if (i < NG * HID) g_pooled[i] = 0.f;
    if (i < NG) g_cnt[i] = 0.f;
}

// -------- degree (incoming; self-loop added later) --------
__global__ void k_degi(const int* __restrict__ dst) {
    int e = blockIdx.x * blockDim.x + threadIdx.x;
    if (e >= NE) return;
    atomicAdd(&g_degi[dst[e]], 1);
}

// -------- 2-level exclusive scan of degi -> rowptr --------
__global__ void k_scan_a() {
    __shared__ int sh[256];
    int i = blockIdx.x * 256 + threadIdx.x;
    int v = (i < NN) ? g_degi[i] : 0;
    sh[threadIdx.x] = v;
    __syncthreads();
    for (int off = 1; off < 256; off <<= 1) {
        int t = (threadIdx.x >= off) ? sh[threadIdx.x - off] : 0;
        __syncthreads();
        sh[threadIdx.x] += t;
        __syncthreads();
    }
    if (i < NN) g_rowptr[i] = sh[threadIdx.x] - v;   // exclusive within block
    if (threadIdx.x == 255) g_bsum[blockIdx.x] = sh[255];
}

__global__ void k_scan_b() {            // single block, 512 threads
    __shared__ int sh[512];
    int v = (threadIdx.x < NBLK) ? g_bsum[threadIdx.x] : 0;
    sh[threadIdx.x] = v;
    __syncthreads();
    for (int off = 1; off < 512; off <<= 1) {
        int t = (threadIdx.x >= off) ? sh[threadIdx.x - off] : 0;
        __syncthreads();
        sh[threadIdx.x] += t;
        __syncthreads();
    }
    if (threadIdx.x < NBLK) g_bsum[threadIdx.x] = sh[threadIdx.x] - v;  // exclusive
}

__global__ void k_scan_c() {
    int i = blockIdx.x * blockDim.x + threadIdx.x;
    if (i >= NN) return;
    int r = g_rowptr[i] + g_bsum[i >> 8];
    g_rowptr[i] = r;
    g_cursor[i] = r;
    g_dinv[i] = rsqrtf((float)g_degi[i] + 1.0f);   // +1 self-loop
}

// -------- scatter edges into CSR slots: (src, norm-weight) --------
__global__ void k_scatter(const int* __restrict__ src, const int* __restrict__ dst) {
    int e = blockIdx.x * blockDim.x + threadIdx.x;
    if (e >= NE) return;
    int s = __ldg(src + e);
    int d = __ldg(dst + e);
    int slot = atomicAdd(&g_cursor[d], 1);
    float w = g_dinv[s] * g_dinv[d];
    g_csr[slot] = make_uint2((unsigned)s, __float_as_uint(w));
}

// -------- lin1: bufA = x @ W1 (K=5); 4 channels/thread --------
__global__ void k_lin1(const float* __restrict__ x, const float* __restrict__ W1) {
    int idx = blockIdx.x * blockDim.x + threadIdx.x;   // over NN*16
    if (idx >= NN * 16) return;
    int n = idx >> 4, c4 = (idx & 15) * 4;
    float xr[INC];
#pragma unroll
    for (int k = 0; k < INC; k++) xr[k] = __ldg(x + n * INC + k);
    float4 acc = make_float4(0.f, 0.f, 0.f, 0.f);
#pragma unroll
    for (int k = 0; k < INC; k++) {
        float4 w = __ldg((const float4*)(W1 + k * HID + c4));
        acc.x += xr[k] * w.x; acc.y += xr[k] * w.y;
        acc.z += xr[k] * w.z; acc.w += xr[k] * w.w;
    }
    *(float4*)(g_bufA + (size_t)n * HID + c4) = acc;
}

// -------- gather-side aggregation, layer 1: bufB = relu(sum + self + b1) --
__global__ void k_agg1(const float* __restrict__ b1) {
    int t = blockIdx.x * blockDim.x + threadIdx.x;   // NN*16 exact multiple? pad
    int n = t >> 4;
    if (n >= NN) return;
    int l = t & 15;
    int i = g_rowptr[n];
    int end = i + g_degi[n];
    float4 acc = make_float4(0.f, 0.f, 0.f, 0.f);
    for (; i + 2 <= end; i += 2) {
        uint2 e0 = __ldg(&g_csr[i]);
        uint2 e1 = __ldg(&g_csr[i + 1]);
        float4 v0 = __ldg((const float4*)(g_bufA + (size_t)e0.x * HID) + l);
        float4 v1 = __ldg((const float4*)(g_bufA + (size_t)e1.x * HID) + l);
        float w0 = __uint_as_float(e0.y), w1 = __uint_as_float(e1.y);
        acc.x = fmaf(v0.x, w0, fmaf(v1.x, w1, acc.x));
        acc.y = fmaf(v0.y, w0, fmaf(v1.y, w1, acc.y));
        acc.z = fmaf(v0.z, w0, fmaf(v1.z, w1, acc.z));
        acc.w = fmaf(v0.w, w0, fmaf(v1.w, w1, acc.w));
    }
    if (i < end) {
        uint2 e0 = __ldg(&g_csr[i]);
        float4 v0 = __ldg((const float4*)(g_bufA + (size_t)e0.x * HID) + l);
        float w0 = __uint_as_float(e0.y);
        acc.x = fmaf(v0.x, w0, acc.x); acc.y = fmaf(v0.y, w0, acc.y);
        acc.z = fmaf(v0.z, w0, acc.z); acc.w = fmaf(v0.w, w0, acc.w);
    }
    float di = g_dinv[n];
    float sw = di * di;
    float4 lin = ((const float4*)g_bufA)[n * 16 + l];
    float4 bb = __ldg((const float4*)b1 + l);
    float4 r;
    r.x = fmaxf(fmaf(lin.x, sw, acc.x) + bb.x, 0.f);
    r.y = fmaxf(fmaf(lin.y, sw, acc.y) + bb.y, 0.f);
    r.z = fmaxf(fmaf(lin.z, sw, acc.z) + bb.z, 0.f);
    r.w = fmaxf(fmaf(lin.w, sw, acc.w) + bb.w, 0.f);
    ((float4*)g_bufB)[n * 16 + l] = r;
}

// -------- lin2: bufC = bufB @ W2 (64 nodes/block, 128 thr) --------
__global__ void __launch_bounds__(128) k_lin2(const float* __restrict__ W2) {
    __shared__ float Ws[HID * HID];
    for (int i = threadIdx.x; i < HID * HID; i += 128) Ws[i] = W2[i];
    __syncthreads();
    int nb = blockIdx.x * 64;
    int ng = threadIdx.x >> 3;
    int c8 = (threadIdx.x & 7) * 8;
    int n0 = nb + ng;
    const float* h0 = g_bufB + (size_t)min(n0,      NN - 1) * HID;
    const float* h1 = g_bufB + (size_t)min(n0 + 16, NN - 1) * HID;
    const float* h2 = g_bufB + (size_t)min(n0 + 32, NN - 1) * HID;
    const float* h3 = g_bufB + (size_t)min(n0 + 48, NN - 1) * HID;
    float a[4][8];
#pragma unroll
    for (int j = 0; j < 4; j++)
#pragma unroll
        for (int c = 0; c < 8; c++) a[j][c] = 0.f;
#pragma unroll 4
    for (int k = 0; k < HID; k++) {
        float4 w0 = *(const float4*)(Ws + k * HID + c8);
        float4 w1 = *(const float4*)(Ws + k * HID + c8 + 4);
        float hv[4] = {__ldg(h0 + k), __ldg(h1 + k), __ldg(h2 + k), __ldg(h3 + k)};
#pragma unroll
        for (int j = 0; j < 4; j++) {
            a[j][0] += hv[j] * w0.x; a[j][1] += hv[j] * w0.y;
            a[j][2] += hv[j] * w0.z; a[j][3] += hv[j] * w0.w;
            a[j][4] += hv[j] * w1.x; a[j][5] += hv[j] * w1.y;
            a[j][6] += hv[j] * w1.z; a[j][7] += hv[j] * w1.w;
        }
    }
#pragma unroll
    for (int j = 0; j < 4; j++) {
        int n = n0 + 16 * j;
        if (n < NN) {
            float* o = g_bufC + (size_t)n * HID + c8;
            *(float4*)o       = make_float4(a[j][0], a[j][1], a[j][2], a[j][3]);
            *(float4*)(o + 4) = make_float4(a[j][4], a[j][5], a[j][6], a[j][7]);
        }
    }
}

// -------- gather-side aggregation, layer 2, fused relu + mean-pool RED ----
__global__ void k_agg2(const float* __restrict__ b2, const int* __restrict__ batch) {
    int t = blockIdx.x * blockDim.x + threadIdx.x;
    int n = t >> 4;
    if (n >= NN) return;
    int l = t & 15;
    int i = g_rowptr[n];
    int end = i + g_degi[n];
    float4 acc = make_float4(0.f, 0.f, 0.f, 0.f);
    for (; i + 2 <= end; i += 2) {
        uint2 e0 = __ldg(&g_csr[i]);
        uint2 e1 = __ldg(&g_csr[i + 1]);
        float4 v0 = __ldg((const float4*)(g_bufC + (size_t)e0.x * HID) + l);
        float4 v1 = __ldg((const float4*)(g_bufC + (size_t)e1.x * HID) + l);
        float w0 = __uint_as_float(e0.y), w1 = __uint_as_float(e1.y);
        acc.x = fmaf(v0.x, w0, fmaf(v1.x, w1, acc.x));
        acc.y = fmaf(v0.y, w0, fmaf(v1.y, w1, acc.y));
        acc.z = fmaf(v0.z, w0, fmaf(v1.z, w1, acc.z));
        acc.w = fmaf(v0.w, w0, fmaf(v1.w, w1, acc.w));
    }
    if (i < end) {
        uint2 e0 = __ldg(&g_csr[i]);
        float4 v0 = __ldg((const float4*)(g_bufC + (size_t)e0.x * HID) + l);
        float w0 = __uint_as_float(e0.y);
        acc.x = fmaf(v0.x, w0, acc.x); acc.y = fmaf(v0.y, w0, acc.y);
        acc.z = fmaf(v0.z, w0, acc.z); acc.w = fmaf(v0.w, w0, acc.w);
    }
    float di = g_dinv[n];
    float sw = di * di;
    float4 lin = ((const float4*)g_bufC)[n * 16 + l];
    float4 bb = __ldg((const float4*)b2 + l);
    float hx = fmaxf(fmaf(lin.x, sw, acc.x) + bb.x, 0.f);
    float hy = fmaxf(fmaf(lin.y, sw, acc.y) + bb.y, 0.f);
    float hz = fmaxf(fmaf(lin.z, sw, acc.z) + bb.z, 0.f);
    float hw = fmaxf(fmaf(lin.w, sw, acc.w) + bb.w, 0.f);
    int g = __ldg(batch + n);
    red4(&g_pooled[g * HID + l * 4], hx, hy, hz, hw);
    if (l == 0) atomicAdd(&g_cnt[g], 1.0f);
}

// -------- final: out[g][o] = (pooled[g]@Wfc)[o]/cnt[g] + bfc[o] -----------
__global__ void k_final(const float* __restrict__ Wfc,
                        const float* __restrict__ bfc,
                        float* __restrict__ out) {
    int t = threadIdx.x;                // 512 threads: (g, o)
    int g = t >> 1, o = t & 1;
    float acc = 0.f;
#pragma unroll
    for (int c = 0; c < HID; c++)
        acc += g_pooled[g * HID + c] * __ldg(Wfc + c * 2 + o);
    float cnt = fmaxf(g_cnt[g], 1.0f);
    out[g * 2 + o] = acc / cnt + __ldg(bfc + o);
}

extern "C" void kernel_launch(void* const* d_in, const int* in_sizes, int n_in,
                              void* d_out, int out_size) {
    const float* x     = (const float*)d_in[0];
    const int*   ei    = (const int*)d_in[1];     // int32 (JAX x64 disabled)
    const int*   batch = (const int*)d_in[2];
    const float* W1    = (const float*)d_in[3];
    const float* b1    = (const float*)d_in[4];
    const float* W2    = (const float*)d_in[5];
    const float* b2    = (const float*)d_in[6];
    const float* Wfc   = (const float*)d_in[7];
    const float* bfc   = (const float*)d_in[8];
    float*       out   = (float*)d_out;

    const int* src = ei;
    const int* dst = ei + NE;

    const int T = 256;
    k_init<<<(NN + T - 1) / T, T>>>();
    k_degi<<<(NE + T - 1) / T, T>>>(dst);
    k_scan_a<<<NBLK, 256>>>();
    k_scan_b<<<1, 512>>>();
    k_scan_c<<<(NN + T - 1) / T, T>>>();
    k_scatter<<<(NE + T - 1) / T, T>>>(src, dst);
    k_lin1<<<(NN * 16 + T - 1) / T, T>>>(x, W1);
    k_agg1<<<(NN * 16 + T - 1) / T, T>>>(b1);
    k_lin2<<<(NN + 63) / 64, 128>>>(W2);
    k_agg2<<<(NN * 16 + T - 1) / T, T>>>(b2, batch);
    k_final<<<1, 512>>>(Wfc, bfc, out);
}

// round 10
// speedup vs baseline: 1.9700x; 1.1223x over previous
#include <cuda_runtime.h>
#include <cstdint>

#define NN 100000
#define NE 1200000
#define NG 256
#define HID 64
#define INC 5
#define NBLK ((NN + 255) / 256)   // 391 scan blocks

// -------- scratch (device globals; no allocation allowed) --------
__device__ __align__(256) float g_bufA[NN * HID];   // aggX [NN][8] (first 800K floats)
__device__ __align__(256) float g_bufB[NN * HID];   // xpre [NN][8] then aggH [NN][64]
__device__ __align__(256) float g_bufC[NN * HID];   // h1pre [NN][64]
__device__ __align__(256) int   g_degi[NN];
__device__ __align__(256) int   g_rowptr[NN];
__device__ __align__(256) int   g_cursor[NN];
__device__ __align__(256) int   g_bsum[512];
__device__ __align__(256) float g_dinv[NN];
__device__ __align__(256) int   g_csri[NE];         // src per edge, dst-grouped
__device__ __align__(256) float g_pooled[NG * HID];
__device__ __align__(256) float g_cnt[NG];

__device__ __forceinline__ void red4(float* p, float a, float b, float c, float d) {
    asm volatile("red.global.add.v4.f32 [%0], {%1,%2,%3,%4};"
                 :: "l"(p), "f"(a), "f"(b), "f"(c), "f"(d) : "memory");
}

// -------- init: zero degi + pooled + cnt --------
__global__ void k_init() {
    int i = blockIdx.x * blockDim.x + threadIdx.x;
    if (i < NN) g_degi[i] = 0;
    if (i < NG * HID) g_pooled[i] = 0.f;
    if (i < NG) g_cnt[i] = 0.f;
}

// -------- degree (incoming; self-loop handled analytically) --------
__global__ void k_degi(const int* __restrict__ dst) {
    int e = blockIdx.x * blockDim.x + threadIdx.x;
    if (e >= NE) return;
    atomicAdd(&g_degi[dst[e]], 1);
}

// -------- 2-level exclusive scan of degi -> rowptr --------
__global__ void k_scan_a() {
    __shared__ int sh[256];
    int i = blockIdx.x * 256 + threadIdx.x;
    int v = (i < NN) ? g_degi[i] : 0;
    sh[threadIdx.x] = v;
    __syncthreads();
    for (int off = 1; off < 256; off <<= 1) {
        int t = (threadIdx.x >= off) ? sh[threadIdx.x - off] : 0;
        __syncthreads();
        sh[threadIdx.x] += t;
        __syncthreads();
    }
    if (i < NN) g_rowptr[i] = sh[threadIdx.x] - v;
    if (threadIdx.x == 255) g_bsum[blockIdx.x] = sh[255];
}

__global__ void k_scan_b() {            // single block, 512 threads
    __shared__ int sh[512];
    int v = (threadIdx.x < NBLK) ? g_bsum[threadIdx.x] : 0;
    sh[threadIdx.x] = v;
    __syncthreads();
    for (int off = 1; off < 512; off <<= 1) {
        int t = (threadIdx.x >= off) ? sh[threadIdx.x - off] : 0;
        __syncthreads();
        sh[threadIdx.x] += t;
        __syncthreads();
    }
    if (threadIdx.x < NBLK) g_bsum[threadIdx.x] = sh[threadIdx.x] - v;
}

// -------- scan_c: finalize rowptr/cursor, dinv, xpre = dinv*x, graph counts
__global__ void k_scan_c(const float* __restrict__ x, const int* __restrict__ batch) {
    int i = blockIdx.x * blockDim.x + threadIdx.x;
    if (i >= NN) return;
    int r = g_rowptr[i] + g_bsum[i >> 8];
    g_rowptr[i] = r;
    g_cursor[i] = r;
    float di = rsqrtf((float)g_degi[i] + 1.0f);   // +1 = self-loop
    g_dinv[i] = di;
    const float* xr = x + i * INC;
    float* xp = g_bufB + i * 8;
    xp[0] = di * __ldg(xr + 0);
    xp[1] = di * __ldg(xr + 1);
    xp[2] = di * __ldg(xr + 2);
    xp[3] = di * __ldg(xr + 3);
    xp[4] = di * __ldg(xr + 4);
    xp[5] = 0.f; xp[6] = 0.f; xp[7] = 0.f;
    atomicAdd(&g_cnt[__ldg(batch + i)], 1.0f);
}

// -------- scatter edges into CSR slots (src only) --------
__global__ void k_scatter(const int* __restrict__ src, const int* __restrict__ dst) {
    int e = blockIdx.x * blockDim.x + threadIdx.x;
    if (e >= NE) return;
    int s = __ldg(src + e);
    int d = __ldg(dst + e);
    int slot = atomicAdd(&g_cursor[d], 1);
    g_csri[slot] = s;
}

// -------- layer-1 aggregation in INPUT space: aggX = dinv*(sum xpre[src] + xpre[n])
__global__ void k_aggx() {
    int n = blockIdx.x * blockDim.x + threadIdx.x;
    if (n >= NN) return;
    int i = g_rowptr[n];
    int end = i + g_degi[n];
    float4 a0 = make_float4(0.f, 0.f, 0.f, 0.f);
    float a4 = 0.f;
    for (; i + 2 <= end; i += 2) {
        int s0 = __ldg(g_csri + i);
        int s1 = __ldg(g_csri + i + 1);
        float4 p0 = __ldg((const float4*)(g_bufB + s0 * 8));
        float  q0 = __ldg(g_bufB + s0 * 8 + 4);
        float4 p1 = __ldg((const float4*)(g_bufB + s1 * 8));
        float  q1 = __ldg(g_bufB + s1 * 8 + 4);
        a0.x += p0.x + p1.x; a0.y += p0.y + p1.y;
        a0.z += p0.z + p1.z; a0.w += p0.w + p1.w;
        a4 += q0 + q1;
    }
    if (i < end) {
        int s0 = __ldg(g_csri + i);
        float4 p0 = __ldg((const float4*)(g_bufB + s0 * 8));
        a0.x += p0.x; a0.y += p0.y; a0.z += p0.z; a0.w += p0.w;
        a4 += __ldg(g_bufB + s0 * 8 + 4);
    }
    // self term
    float4 ps = *(const float4*)(g_bufB + n * 8);
    float  qs = g_bufB[n * 8 + 4];
    float di = g_dinv[n];
    float* o = g_bufA + n * 8;
    *(float4*)o = make_float4(di * (a0.x + ps.x), di * (a0.y + ps.y),
                              di * (a0.z + ps.z), di * (a0.w + ps.w));
    o[4] = di * (a4 + qs);
}

// -------- lin1: h1pre = dinv * relu(aggX @ W1 + b1); 4 channels/thread ----
__global__ void k_lin1(const float* __restrict__ W1, const float* __restrict__ b1) {
    int idx = blockIdx.x * blockDim.x + threadIdx.x;   // over NN*16
    if (idx >= NN * 16) return;
    int n = idx >> 4, c4 = (idx & 15) * 4;
    float xr[INC];
#pragma unroll
    for (int k = 0; k < INC; k++) xr[k] = __ldg(g_bufA + n * 8 + k);
    float4 acc = __ldg((const float4*)(b1 + c4));
#pragma unroll
    for (int k = 0; k < INC; k++) {
        float4 w = __ldg((const float4*)(W1 + k * HID + c4));
        acc.x = fmaf(xr[k], w.x, acc.x); acc.y = fmaf(xr[k], w.y, acc.y);
        acc.z = fmaf(xr[k], w.z, acc.z); acc.w = fmaf(xr[k], w.w, acc.w);
    }
    float di = g_dinv[n];
    acc.x = di * fmaxf(acc.x, 0.f); acc.y = di * fmaxf(acc.y, 0.f);
    acc.z = di * fmaxf(acc.z, 0.f); acc.w = di * fmaxf(acc.w, 0.f);
    *(float4*)(g_bufC + (size_t)n * HID + c4) = acc;
}

// -------- layer-2 aggregation: aggH = dinv*(sum h1pre[src] + h1pre[n]) ----
__global__ void k_aggh() {
    int t = blockIdx.x * blockDim.x + threadIdx.x;   // NN*16 threads
    int n = t >> 4;
    if (n >= NN) return;
    int l = t & 15;
    int i = g_rowptr[n];
    int end = i + g_degi[n];
    float4 acc = make_float4(0.f, 0.f, 0.f, 0.f);
    for (; i + 2 <= end; i += 2) {
        int s0 = __ldg(g_csri + i);
        int s1 = __ldg(g_csri + i + 1);
        float4 v0 = __ldg((const float4*)(g_bufC + (size_t)s0 * HID) + l);
        float4 v1 = __ldg((const float4*)(g_bufC + (size_t)s1 * HID) + l);
        acc.x += v0.x + v1.x; acc.y += v0.y + v1.y;
        acc.z += v0.z + v1.z; acc.w += v0.w + v1.w;
    }
    if (i < end) {
        int s0 = __ldg(g_csri + i);
        float4 v0 = __ldg((const float4*)(g_bufC + (size_t)s0 * HID) + l);
        acc.x += v0.x; acc.y += v0.y; acc.z += v0.z; acc.w += v0.w;
    }
    float4 vs = ((const float4*)g_bufC)[n * 16 + l];   // self (h1pre[n])
    float di = g_dinv[n];
    ((float4*)g_bufB)[n * 16 + l] = make_float4(
        di * (acc.x + vs.x), di * (acc.y + vs.y),
        di * (acc.z + vs.z), di * (acc.w + vs.w));
}

// -------- lin2 fused with relu + mean-pool RED (no h2 buffer) -------------
__global__ void __launch_bounds__(128) k_lin2pool(const float* __restrict__ W2,
                                                  const float* __restrict__ b2,
                                                  const int* __restrict__ batch) {
    __shared__ float Ws[HID * HID];
    for (int i = threadIdx.x; i < HID * HID; i += 128) Ws[i] = W2[i];
    __syncthreads();
    int nb = blockIdx.x * 64;
    int ng = threadIdx.x >> 3;
    int c8 = (threadIdx.x & 7) * 8;
    int n0 = nb + ng;
    const float* h0 = g_bufB + (size_t)min(n0,      NN - 1) * HID;
    const float* h1 = g_bufB + (size_t)min(n0 + 16, NN - 1) * HID;
    const float* h2 = g_bufB + (size_t)min(n0 + 32, NN - 1) * HID;
    const float* h3 = g_bufB + (size_t)min(n0 + 48, NN - 1) * HID;
    float a[4][8];
#pragma unroll
    for (int j = 0; j < 4; j++)
#pragma unroll
        for (int c = 0; c < 8; c++) a[j][c] = 0.f;
#pragma unroll 4
    for (int k = 0; k < HID; k++) {
        float4 w0 = *(const float4*)(Ws + k * HID + c8);
        float4 w1 = *(const float4*)(Ws + k * HID + c8 + 4);
        float hv[4] = {__ldg(h0 + k), __ldg(h1 + k), __ldg(h2 + k), __ldg(h3 + k)};
#pragma unroll
        for (int j = 0; j < 4; j++) {
            a[j][0] = fmaf(hv[j], w0.x, a[j][0]); a[j][1] = fmaf(hv[j], w0.y, a[j][1]);
            a[j][2] = fmaf(hv[j], w0.z, a[j][2]); a[j][3] = fmaf(hv[j], w0.w, a[j][3]);
            a[j][4] = fmaf(hv[j], w1.x, a[j][4]); a[j][5] = fmaf(hv[j], w1.y, a[j][5]);
            a[j][6] = fmaf(hv[j], w1.z, a[j][6]); a[j][7] = fmaf(hv[j], w1.w, a[j][7]);
        }
    }
    float4 bb0 = __ldg((const float4*)(b2 + c8));
    float4 bb1 = __ldg((const float4*)(b2 + c8 + 4));
#pragma unroll
    for (int j = 0; j < 4; j++) {
        int n = n0 + 16 * j;
        if (n < NN) {
            int g = __ldg(batch + n);
            float r0 = fmaxf(a[j][0] + bb0.x, 0.f);
            float r1 = fmaxf(a[j][1] + bb0.y, 0.f);
            float r2 = fmaxf(a[j][2] + bb0.z, 0.f);
            float r3 = fmaxf(a[j][3] + bb0.w, 0.f);
            float r4 = fmaxf(a[j][4] + bb1.x, 0.f);
            float r5 = fmaxf(a[j][5] + bb1.y, 0.f);
            float r6 = fmaxf(a[j][6] + bb1.z, 0.f);
            float r7 = fmaxf(a[j][7] + bb1.w, 0.f);
            red4(&g_pooled[g * HID + c8],     r0, r1, r2, r3);
            red4(&g_pooled[g * HID + c8 + 4], r4, r5, r6, r7);
        }
    }
}

// -------- final: out[g][o] = (pooled[g]@Wfc)[o]/cnt[g] + bfc[o] -----------
__global__ void k_final(const float* __restrict__ Wfc,
                        const float* __restrict__ bfc,
                        float* __restrict__ out) {
    int t = threadIdx.x;                // 512 threads: (g, o)
    int g = t >> 1, o = t & 1;
    float acc = 0.f;
#pragma unroll
    for (int c = 0; c < HID; c++)
        acc += g_pooled[g * HID + c] * __ldg(Wfc + c * 2 + o);
    float cnt = fmaxf(g_cnt[g], 1.0f);
    out[g * 2 + o] = acc / cnt + __ldg(bfc + o);
}

extern "C" void kernel_launch(void* const* d_in, const int* in_sizes, int n_in,
                              void* d_out, int out_size) {
    const float* x     = (const float*)d_in[0];
    const int*   ei    = (const int*)d_in[1];     // int32 (JAX x64 disabled)
    const int*   batch = (const int*)d_in[2];
    const float* W1    = (const float*)d_in[3];
    const float* b1    = (const float*)d_in[4];
    const float* W2    = (const float*)d_in[5];
    const float* b2    = (const float*)d_in[6];
    const float* Wfc   = (const float*)d_in[7];
    const float* bfc   = (const float*)d_in[8];
    float*       out   = (float*)d_out;

    const int* src = ei;
    const int* dst = ei + NE;

    const int T = 256;
    k_init<<<(NN + T - 1) / T, T>>>();
    k_degi<<<(NE + T - 1) / T, T>>>(dst);
    k_scan_a<<<NBLK, 256>>>();
    k_scan_b<<<1, 512>>>();
    k_scan_c<<<(NN + T - 1) / T, T>>>(x, batch);
    k_scatter<<<(NE + T - 1) / T, T>>>(src, dst);
    k_aggx<<<(NN + T - 1) / T, T>>>();
    k_lin1<<<(NN * 16 + T - 1) / T, T>>>(W1, b1);
    k_aggh<<<(NN * 16 + T - 1) / T, T>>>();
    k_lin2pool<<<(NN + 63) / 64, 128>>>(W2, b2, batch);
    k_final<<<1, 512>>>(Wfc, bfc, out);
}

// round 12
// speedup vs baseline: 2.1104x; 1.0713x over previous
#include <cuda_runtime.h>
#include <cuda_fp16.h>
#include <cstdint>

#define NN 100000
#define NE 1200000
#define NG 256
#define HID 64
#define INC 5
#define NBLK ((NN + 255) / 256)

// -------- scratch (device globals; no allocation allowed) --------
__device__ __align__(256) __half g_xpre[NN * 8];     // dinv*x, 5 used of 8 halves
__device__ __align__(256) float  g_aggx[NN * 8];     // layer-1 aggregated input (5 used)
__device__ __align__(256) __half g_h1[NN * HID];     // h1pre = dinv*relu(lin1) fp16
__device__ __align__(256) float  g_aggh[NN * HID];   // layer-2 aggregated hidden
__device__ __align__(256) int    g_degi[NN];
__device__ __align__(256) int    g_rowptr[NN];
__device__ __align__(256) int    g_cursor[NN];
__device__ __align__(256) float  g_dinv[NN];
__device__ __align__(256) int    g_csri[NE];         // src per edge, dst-grouped
__device__ __align__(256) float  g_pooled[NG * HID];
__device__ __align__(256) float  g_cnt[NG];
__device__ int g_gbase;

__device__ __forceinline__ void red4(float* p, float a, float b, float c, float d) {
    asm volatile("red.global.add.v4.f32 [%0], {%1,%2,%3,%4};"
                 :: "l"(p), "f"(a), "f"(b), "f"(c), "f"(d) : "memory");
}

// -------- init --------
__global__ void k_init() {
    int i = blockIdx.x * blockDim.x + threadIdx.x;
    if (i < NN) g_degi[i] = 0;
    if (i < NG * HID) g_pooled[i] = 0.f;
    if (i < NG) g_cnt[i] = 0.f;
    if (i == 0) g_gbase = 0;
}

// -------- degree (incoming; self-loop handled analytically) --------
__global__ void k_degi(const int* __restrict__ dst) {
    int e = blockIdx.x * blockDim.x + threadIdx.x;
    if (e >= NE) return;
    atomicAdd(&g_degi[dst[e]], 1);
}

// -------- single-pass scan: block scan + atomic base; fused node prep ----
__global__ void k_scan(const float* __restrict__ x, const int* __restrict__ batch) {
    __shared__ int sh[256];
    __shared__ int sbase;
    int i = blockIdx.x * 256 + threadIdx.x;
    int v = (i < NN) ? g_degi[i] : 0;
    sh[threadIdx.x] = v;
    __syncthreads();
    for (int off = 1; off < 256; off <<= 1) {
        int t = (threadIdx.x >= off) ? sh[threadIdx.x - off] : 0;
        __syncthreads();
        sh[threadIdx.x] += t;
        __syncthreads();
    }
    if (threadIdx.x == 255) sbase = atomicAdd(&g_gbase, sh[255]);
    __syncthreads();
    if (i >= NN) return;
    int r = sbase + sh[threadIdx.x] - v;      // exclusive offset for node i
    g_rowptr[i] = r;
    g_cursor[i] = r;
    float di = rsqrtf((float)v + 1.0f);       // +1 = self-loop
    g_dinv[i] = di;
    const float* xr = x + i * INC;
    __half2 h0 = __floats2half2_rn(di * __ldg(xr + 0), di * __ldg(xr + 1));
    __half2 h1 = __floats2half2_rn(di * __ldg(xr + 2), di * __ldg(xr + 3));
    __half2 h2 = __floats2half2_rn(di * __ldg(xr + 4), 0.f);
    uint4 u;
    u.x = *(unsigned*)&h0; u.y = *(unsigned*)&h1;
    u.z = *(unsigned*)&h2; u.w = 0u;
    *(uint4*)(g_xpre + i * 8) = u;
    atomicAdd(&g_cnt[__ldg(batch + i)], 1.0f);
}

// -------- scatter edges into CSR slots (src only) --------
__global__ void k_scatter(const int* __restrict__ src, const int* __restrict__ dst) {
    int e = blockIdx.x * blockDim.x + threadIdx.x;
    if (e >= NE) return;
    int s = __ldg(src + e);
    int d = __ldg(dst + e);
    int slot = atomicAdd(&g_cursor[d], 1);
    g_csri[slot] = s;
}

__device__ __forceinline__ void acc5(uint4 u, float a[5]) {
    float2 f0 = __half22float2(*(__half2*)&u.x);
    float2 f1 = __half22float2(*(__half2*)&u.y);
    float2 f2 = __half22float2(*(__half2*)&u.z);
    a[0] += f0.x; a[1] += f0.y; a[2] += f1.x; a[3] += f1.y; a[4] += f2.x;
}

// -------- layer-1 aggregation: aggX = dinv*(sum xpre[src] + xpre[n]) ------
__global__ void k_aggx() {
    int n = blockIdx.x * blockDim.x + threadIdx.x;
    if (n >= NN) return;
    int i = g_rowptr[n];
    int end = i + g_degi[n];
    float a[5] = {0.f, 0.f, 0.f, 0.f, 0.f};
    for (; i + 2 <= end; i += 2) {
        int s0 = __ldg(g_csri + i);
        int s1 = __ldg(g_csri + i + 1);
        acc5(__ldg((const uint4*)(g_xpre + s0 * 8)), a);
        acc5(__ldg((const uint4*)(g_xpre + s1 * 8)), a);
    }
    if (i < end)
        acc5(__ldg((const uint4*)(g_xpre + __ldg(g_csri + i) * 8)), a);
    acc5(*(const uint4*)(g_xpre + n * 8), a);   // self term
    float di = g_dinv[n];
    float* o = g_aggx + n * 8;
    *(float4*)o = make_float4(di * a[0], di * a[1], di * a[2], di * a[3]);
    o[4] = di * a[4];
}

// -------- lin1: h1pre = dinv * relu(aggX @ W1 + b1) -> fp16; 8 ch/thread --
__global__ void k_lin1(const float* __restrict__ W1, const float* __restrict__ b1) {
    int idx = blockIdx.x * blockDim.x + threadIdx.x;   // NN*8 threads
    if (idx >= NN * 8) return;
    int n = idx >> 3, c8 = (idx & 7) * 8;
    float xr[INC];
#pragma unroll
    for (int k = 0; k < INC; k++) xr[k] = __ldg(g_aggx + n * 8 + k);
    float4 a0 = __ldg((const float4*)(b1 + c8));
    float4 a1 = __ldg((const float4*)(b1 + c8 + 4));
#pragma unroll
    for (int k = 0; k < INC; k++) {
        float4 w0 = __ldg((const float4*)(W1 + k * HID + c8));
        float4 w1 = __ldg((const float4*)(W1 + k * HID + c8 + 4));
        a0.x = fmaf(xr[k], w0.x, a0.x); a0.y = fmaf(xr[k], w0.y, a0.y);
        a0.z = fmaf(xr[k], w0.z, a0.z); a0.w = fmaf(xr[k], w0.w, a0.w);
        a1.x = fmaf(xr[k], w1.x, a1.x); a1.y = fmaf(xr[k], w1.y, a1.y);
        a1.z = fmaf(xr[k], w1.z, a1.z); a1.w = fmaf(xr[k], w1.w, a1.w);
    }
    float di = g_dinv[n];
    __half2 p0 = __floats2half2_rn(di * fmaxf(a0.x, 0.f), di * fmaxf(a0.y, 0.f));
    __half2 p1 = __floats2half2_rn(di * fmaxf(a0.z, 0.f), di * fmaxf(a0.w, 0.f));
    __half2 p2 = __floats2half2_rn(di * fmaxf(a1.x, 0.f), di * fmaxf(a1.y, 0.f));
    __half2 p3 = __floats2half2_rn(di * fmaxf(a1.z, 0.f), di * fmaxf(a1.w, 0.f));
    uint4 u;
    u.x = *(unsigned*)&p0; u.y = *(unsigned*)&p1;
    u.z = *(unsigned*)&p2; u.w = *(unsigned*)&p3;
    *(uint4*)(g_h1 + (size_t)n * HID + c8) = u;
}

__device__ __forceinline__ void acc8(uint4 u, float a[8]) {
    float2 f0 = __half22float2(*(__half2*)&u.x);
    float2 f1 = __half22float2(*(__half2*)&u.y);
    float2 f2 = __half22float2(*(__half2*)&u.z);
    float2 f3 = __half22float2(*(__half2*)&u.w);
    a[0] += f0.x; a[1] += f0.y; a[2] += f1.x; a[3] += f1.y;
    a[4] += f2.x; a[5] += f2.y; a[6] += f3.x; a[7] += f3.y;
}

// -------- layer-2 aggregation: aggH = dinv*(sum h1pre[src] + h1pre[n]) ----
// 8 lanes/node, each lane covers 8 fp16 channels (16B load per edge).
__global__ void k_aggh() {
    int t = blockIdx.x * blockDim.x + threadIdx.x;   // NN*8 threads
    int n = t >> 3;
    if (n >= NN) return;
    int l = (t & 7) * 8;
    int i = g_rowptr[n];
    int end = i + g_degi[n];
    float a[8] = {0.f, 0.f, 0.f, 0.f, 0.f, 0.f, 0.f, 0.f};
    for (; i + 2 <= end; i += 2) {
        int s0 = __ldg(g_csri + i);
        int s1 = __ldg(g_csri + i + 1);
        acc8(__ldg((const uint4*)(g_h1 + (size_t)s0 * HID + l)), a);
        acc8(__ldg((const uint4*)(g_h1 + (size_t)s1 * HID + l)), a);
    }
    if (i < end)
        acc8(__ldg((const uint4*)(g_h1 + (size_t)__ldg(g_csri + i) * HID + l)), a);
    acc8(*(const uint4*)(g_h1 + (size_t)n * HID + l), a);   // self
    float di = g_dinv[n];
    float* o = g_aggh + (size_t)n * HID + l;
    *(float4*)o       = make_float4(di * a[0], di * a[1], di * a[2], di * a[3]);
    *(float4*)(o + 4) = make_float4(di * a[4], di * a[5], di * a[6], di * a[7]);
}

// -------- lin2 fused with relu + mean-pool RED (no h2 buffer) -------------
__global__ void __launch_bounds__(128) k_lin2pool(const float* __restrict__ W2,
                                                  const float* __restrict__ b2,
                                                  const int* __restrict__ batch) {
    __shared__ float Ws[HID * HID];
    for (int i = threadIdx.x; i < HID * HID; i += 128) Ws[i] = W2[i];
    __syncthreads();
    int nb = blockIdx.x * 64;
    int ng = threadIdx.x >> 3;
    int c8 = (threadIdx.x & 7) * 8;
    int n0 = nb + ng;
    const float* h0 = g_aggh + (size_t)min(n0,      NN - 1) * HID;
    const float* h1 = g_aggh + (size_t)min(n0 + 16, NN - 1) * HID;
    const float* h2 = g_aggh + (size_t)min(n0 + 32, NN - 1) * HID;
    const float* h3 = g_aggh + (size_t)min(n0 + 48, NN - 1) * HID;
    float a[4][8];
#pragma unroll
    for (int j = 0; j < 4; j++)
#pragma unroll
        for (int c = 0; c < 8; c++) a[j][c] = 0.f;
#pragma unroll 4
    for (int k = 0; k < HID; k++) {
        float4 w0 = *(const float4*)(Ws + k * HID + c8);
        float4 w1 = *(const float4*)(Ws + k * HID + c8 + 4);
        float hv[4] = {__ldg(h0 + k), __ldg(h1 + k), __ldg(h2 + k), __ldg(h3 + k)};
#pragma unroll
        for (int j = 0; j < 4; j++) {
            a[j][0] = fmaf(hv[j], w0.x, a[j][0]); a[j][1] = fmaf(hv[j], w0.y, a[j][1]);
            a[j][2] = fmaf(hv[j], w0.z, a[j][2]); a[j][3] = fmaf(hv[j], w0.w, a[j][3]);
            a[j][4] = fmaf(hv[j], w1.x, a[j][4]); a[j][5] = fmaf(hv[j], w1.y, a[j][5]);
            a[j][6] = fmaf(hv[j], w1.z, a[j][6]); a[j][7] = fmaf(hv[j], w1.w, a[j][7]);
        }
    }
    float4 bb0 = __ldg((const float4*)(b2 + c8));
    float4 bb1 = __ldg((const float4*)(b2 + c8 + 4));
#pragma unroll
    for (int j = 0; j < 4; j++) {
        int n = n0 + 16 * j;
        if (n < NN) {
            int g = __ldg(batch + n);
            float r0 = fmaxf(a[j][0] + bb0.x, 0.f);
            float r1 = fmaxf(a[j][1] + bb0.y, 0.f);
            float r2 = fmaxf(a[j][2] + bb0.z, 0.f);
            float r3 = fmaxf(a[j][3] + bb0.w, 0.f);
            float r4 = fmaxf(a[j][4] + bb1.x, 0.f);
            float r5 = fmaxf(a[j][5] + bb1.y, 0.f);
            float r6 = fmaxf(a[j][6] + bb1.z, 0.f);
            float r7 = fmaxf(a[j][7] + bb1.w, 0.f);
            red4(&g_pooled[g * HID + c8],     r0, r1, r2, r3);
            red4(&g_pooled[g * HID + c8 + 4], r4, r5, r6, r7);
        }
    }
}

// -------- final: out[g][o] = (pooled[g]@Wfc)[o]/cnt[g] + bfc[o] -----------
__global__ void k_final(const float* __restrict__ Wfc,
                        const float* __restrict__ bfc,
                        float* __restrict__ out) {
    int t = threadIdx.x;                // 512 threads: (g, o)
    int g = t >> 1, o = t & 1;
    float acc = 0.f;
#pragma unroll
    for (int c = 0; c < HID; c++)
        acc += g_pooled[g * HID + c] * __ldg(Wfc + c * 2 + o);
    float cnt = fmaxf(g_cnt[g], 1.0f);
    out[g * 2 + o] = acc / cnt + __ldg(bfc + o);
}

extern "C" void kernel_launch(void* const* d_in, const int* in_sizes, int n_in,
                              void* d_out, int out_size) {
    const float* x     = (const float*)d_in[0];
    const int*   ei    = (const int*)d_in[1];     // int32 (JAX x64 disabled)
    const int*   batch = (const int*)d_in[2];
    const float* W1    = (const float*)d_in[3];
    const float* b1    = (const float*)d_in[4];
    const float* W2    = (const float*)d_in[5];
    const float* b2    = (const float*)d_in[6];
    const float* Wfc   = (const float*)d_in[7];
    const float* bfc   = (const float*)d_in[8];
    float*       out   = (float*)d_out;

    const int* src = ei;
    const int* dst = ei + NE;

    const int T = 256;
    k_init<<<(NN + T - 1) / T, T>>>();
    k_degi<<<(NE + T - 1) / T, T>>>(dst);
    k_scan<<<NBLK, 256>>>(x, batch);
    k_scatter<<<(NE + T - 1) / T, T>>>(src, dst);
    k_aggx<<<(NN + T - 1) / T, T>>>();
    k_lin1<<<(NN * 8 + T - 1) / T, T>>>(W1, b1);
    k_aggh<<<(NN * 8 + T - 1) / T, T>>>();
    k_lin2pool<<<(NN + 63) / 64, 128>>>(W2, b2, batch);
    k_final<<<1, 512>>>(Wfc, bfc, out);
}